// round 1
// baseline (speedup 1.0000x reference)
#include <cuda_runtime.h>
#include <cuda_bf16.h>

#define NN 50000
#define NE 800000
#define DD 64
#define MAXDEG 64

// ---------------- device scratch (no allocations allowed) ----------------
__device__ int   g_src[NE];
__device__ int   g_dst[NE];
__device__ int   g_deg[NN];
__device__ int   g_cur[NN];
__device__ float g_isd[NN];
__device__ int   g_pad[NN * MAXDEG];   // padded CSR: incoming srcs per node
__device__ float g_F0[NN * DD];        // h' (scaled linear output)
__device__ float g_F2[NN * DD];        // layer output (next layer input)
__device__ float g_s1[NN];             // layer-3 scalar h'
__device__ int   g_is64;

// ---------------- setup kernels ----------------
__global__ void k_zero() {
    int i = blockIdx.x * blockDim.x + threadIdx.x;
    if (i < NN) { g_deg[i] = 0; g_cur[i] = 0; }
}

// Detect whether edge_index is int64 or int32: values < 50000, so if int64,
// every odd 32-bit word (high half) of the first 256 entries is zero.
__global__ void k_detect(const int* __restrict__ e32) {
    int v = e32[2 * threadIdx.x + 1];
    int all = __syncthreads_and(v == 0);
    if (threadIdx.x == 0) g_is64 = all;
}

__global__ void k_convert(const void* __restrict__ eraw) {
    int i = blockIdx.x * blockDim.x + threadIdx.x;
    if (i >= NE) return;
    int s, d;
    if (g_is64) {
        const long long* e = (const long long*)eraw;
        s = (int)e[i];
        d = (int)e[NE + i];
    } else {
        const int* e = (const int*)eraw;
        s = e[i];
        d = e[NE + i];
    }
    g_src[i] = s;
    g_dst[i] = d;
    atomicAdd(&g_deg[d], 1);
}

__global__ void k_isd() {
    int i = blockIdx.x * blockDim.x + threadIdx.x;
    if (i < NN) g_isd[i] = rsqrtf((float)g_deg[i] + 1.0f);
}

__global__ void k_bucket() {
    int i = blockIdx.x * blockDim.x + threadIdx.x;
    if (i >= NE) return;
    int d = g_dst[i];
    int p = atomicAdd(&g_cur[d], 1);
    if (p < MAXDEG) g_pad[d * MAXDEG + p] = g_src[i];
}

// ---------------- GEMM: h' = (X @ W^T + b) * isd[row], written to g_F0 ----
// Block: 64 rows x 64 cols, 256 threads, each thread a 4x4 register tile.
__global__ void __launch_bounds__(256) k_gemm(const float* __restrict__ Xext,
                                              const float* __restrict__ W,
                                              const float* __restrict__ B,
                                              int layer) {
    __shared__ float xs[DD][DD + 4];   // xs[k][row]  (transposed)
    __shared__ float ws[DD][DD + 4];   // ws[k][col]  (transposed)
    const float* __restrict__ X = (layer == 0) ? Xext : (const float*)g_F2;

    int tid  = threadIdx.x;
    int row0 = blockIdx.x * DD;

    // cooperative transposed loads (gmem coalesced over idx; smem stride 68 -> conflict-free)
    for (int idx = tid; idx < DD * DD; idx += 256) {
        int c = idx >> 6;
        int k = idx & 63;
        ws[k][c] = W[idx];                    // W[c][k]
        int grow = row0 + c;
        xs[k][c] = (grow < NN) ? X[grow * DD + k] : 0.0f;
    }
    __syncthreads();

    int rg = tid >> 4, cg = tid & 15;
    int r0 = rg * 4, c0 = cg * 4;

    float acc[4][4];
#pragma unroll
    for (int i = 0; i < 4; i++)
#pragma unroll
        for (int j = 0; j < 4; j++) acc[i][j] = 0.0f;

#pragma unroll
    for (int k = 0; k < DD; k++) {
        float4 xv = *(const float4*)&xs[k][r0];
        float4 wv = *(const float4*)&ws[k][c0];
        float ax[4] = {xv.x, xv.y, xv.z, xv.w};
        float aw[4] = {wv.x, wv.y, wv.z, wv.w};
#pragma unroll
        for (int i = 0; i < 4; i++)
#pragma unroll
            for (int j = 0; j < 4; j++) acc[i][j] += ax[i] * aw[j];
    }

    float4 bv = *(const float4*)&B[c0];
    float bb[4] = {bv.x, bv.y, bv.z, bv.w};
#pragma unroll
    for (int i = 0; i < 4; i++) {
        int row = row0 + r0 + i;
        if (row < NN) {
            float s = g_isd[row];
            float4 o;
            o.x = (acc[i][0] + bb[0]) * s;
            o.y = (acc[i][1] + bb[1]) * s;
            o.z = (acc[i][2] + bb[2]) * s;
            o.w = (acc[i][3] + bb[3]) * s;
            *(float4*)&g_F0[row * DD + c0] = o;
        }
    }
}

// ---------------- gather aggregation: out[n] = relu(isd[n]*(h'[n] + sum h'[src])) ----
// 4 nodes per 256-thread block; thread c of a node owns feature c. No atomics.
__global__ void __launch_bounds__(256) k_agg(int do_relu) {
    __shared__ int s_list[4][MAXDEG];
    __shared__ int s_deg[4];
    int tid  = threadIdx.x;
    int ni   = tid >> 6;
    int c    = tid & 63;
    int node = blockIdx.x * 4 + ni;        // NN = 12500*4, always in range

    s_list[ni][c] = g_pad[node * MAXDEG + c];
    if (c == 0) {
        int d = g_deg[node];
        s_deg[ni] = (d < MAXDEG) ? d : MAXDEG;
    }
    __syncthreads();

    int deg = s_deg[ni];
    float acc = g_F0[node * DD + c];       // self-loop term
#pragma unroll 4
    for (int i = 0; i < deg; i++) {
        int s = s_list[ni][i];             // smem broadcast
        acc += g_F0[s * DD + c];           // coalesced 256B row gather (L2-hot)
    }
    float v = acc * g_isd[node];
    if (do_relu) v = fmaxf(v, 0.0f);
    g_F2[node * DD + c] = v;
}

// ---------------- layer 3: scalar dot per node ----------------
__global__ void k_dot(const float* __restrict__ W2, const float* __restrict__ B2) {
    int tid  = threadIdx.x;
    int lane = tid & 31;
    int node = blockIdx.x * 8 + (tid >> 5);    // NN = 6250*8
    float a = g_F2[node * DD + lane]      * __ldg(&W2[lane])
            + g_F2[node * DD + 32 + lane] * __ldg(&W2[32 + lane]);
#pragma unroll
    for (int off = 16; off; off >>= 1) a += __shfl_xor_sync(0xFFFFFFFFu, a, off);
    if (lane == 0) g_s1[node] = (a + __ldg(&B2[0])) * g_isd[node];
}

__global__ void k_out(float* __restrict__ out) {
    int n = blockIdx.x * blockDim.x + threadIdx.x;
    if (n >= NN) return;
    float acc = g_s1[n];
    int d = g_deg[n];
    if (d > MAXDEG) d = MAXDEG;
    const int* lst = &g_pad[n * MAXDEG];
    for (int i = 0; i < d; i++) acc += g_s1[lst[i]];
    out[n] = acc * g_isd[n];
}

// ---------------- launch ----------------
extern "C" void kernel_launch(void* const* d_in, const int* in_sizes, int n_in,
                              void* d_out, int out_size) {
    const float* x  = (const float*)d_in[0];
    const void*  ei = d_in[1];
    const float* W0 = (const float*)d_in[2];
    const float* b0 = (const float*)d_in[3];
    const float* W1 = (const float*)d_in[4];
    const float* b1 = (const float*)d_in[5];
    const float* W2 = (const float*)d_in[6];
    const float* b2 = (const float*)d_in[7];
    float* out = (float*)d_out;

    const int NB_N = (NN + 255) / 256;
    const int NB_E = (NE + 255) / 256;
    const int NB_G = (NN + DD - 1) / DD;   // 782

    k_zero<<<NB_N, 256>>>();
    k_detect<<<1, 256>>>((const int*)ei);
    k_convert<<<NB_E, 256>>>(ei);
    k_isd<<<NB_N, 256>>>();
    k_bucket<<<NB_E, 256>>>();

    // layer 0
    k_gemm<<<NB_G, 256>>>(x, W0, b0, 0);
    k_agg<<<NN / 4, 256>>>(1);
    // layer 1
    k_gemm<<<NB_G, 256>>>(x, W1, b1, 1);
    k_agg<<<NN / 4, 256>>>(1);
    // layer 2 (D_OUT = 1)
    k_dot<<<NN / 8, 256>>>(W2, b2);
    k_out<<<NB_N, 256>>>(out);
}